// round 9
// baseline (speedup 1.0000x reference)
#include <cuda_runtime.h>
#include <stdint.h>

// Problem: B x N fp32 scores. Outputs (concatenated into float d_out):
//   [0, B*N)      portfolio_weights (sparse +softmax(top20), -softmax(bot20))
//   [B*N, 2*B*N)  sorted_indices of argsort(-scores) as float
#define N_COLS 8192
#define NB     1024   // bucket id space (used ids <= 1000)
#define NT     1024   // threads per CTA (one CTA per row)
#define NWARP  32
#define KBUCK  1000   // equal-probability bucket budget

// 13-bit-prefix bucket table. For prefix p = dk >> 19:
//   entry = (base << 5) | cells   (base <= 1000 fits 11 bits, cells <= 31)
//   bucket = base + ((dk & 0x7FFFF) * cells) >> 19
// base = running-max of floor(KBUCK * F(prefix_start)) -> monotone by
// construction; near-equal-probability cells from the exact normal CDF.
__device__ unsigned short g_tab13[8192];

__device__ __forceinline__ float key_to_val(unsigned int dk) {
    unsigned int ukey = ~dk;
    return (ukey & 0x80000000u) ? __uint_as_float(ukey ^ 0x80000000u)
                                : __uint_as_float(~ukey);
}

__device__ __forceinline__ unsigned int desc_key(float x) {
    unsigned int u = __float_as_uint(x);
    unsigned int ukey = (u & 0x80000000u) ? ~u : (u | 0x80000000u);
    return ~ukey;   // ascending key == descending value
}

// Build table in ONE kernel (1 block x 1024 threads).
__global__ void pg_build13() {
    __shared__ unsigned int tmax[NT];
    __shared__ unsigned int fixed[8193];
    int t = threadIdx.x;
    unsigned int v[8];
    unsigned int cm = 0;
#pragma unroll
    for (int i = 0; i < 8; i++) {
        int p = t * 8 + i;
        float x = key_to_val(((unsigned int)p) << 19);
        float F;
        if (!(x == x)) F = (p < 4096) ? 0.f : 1.f;            // NaN prefixes
        else           F = normcdff(-fminf(fmaxf(x, -30.f), 30.f)); // 1-Phi(x)
        int b = (int)floorf(F * (float)KBUCK);
        b = b < 0 ? 0 : (b > KBUCK ? KBUCK : b);
        v[i] = (unsigned int)b;
        cm = max(cm, v[i]);
    }
    tmax[t] = cm;
    __syncthreads();
    for (int d = 1; d < NT; d <<= 1) {
        unsigned int w = (t >= d) ? tmax[t - d] : 0u;
        __syncthreads();
        if (t >= d) tmax[t] = max(tmax[t], w);
        __syncthreads();
    }
    unsigned int run = (t == 0) ? 0u : tmax[t - 1];
#pragma unroll
    for (int i = 0; i < 8; i++) {
        run = max(run, v[i]);
        fixed[t * 8 + i] = run;
    }
    if (t == 0) fixed[8192] = KBUCK;
    __syncthreads();
    for (int p = t; p < 8192; p += NT) {
        unsigned int b0 = fixed[p];
        unsigned int c = fixed[p + 1] - b0;
        if (c > 31u) c = 31u;
        g_tab13[p] = (unsigned short)((b0 << 5) | c);
    }
}

// ---------------------------------------------------------------------------
// SMEM layout (bytes):
//   [0,     32768)  keys  u32[8192]   scattered descending-sort keys (ph 3+)
//   [32768, 49152)  idx16 u16[8192]   scattered original indices    (ph 3+)
//   [49152, 65536)  sidx  u16[8192]   rank->index output (ph 4+)
//                   ALIAS: tab13 u16[8192] bucket table (ph 0-1 only)
//   [65536, 98304)  whist u8[32][1024] per-warp counts -> exclusive offs
//   [98304,102400)  base  u32[1024]    global exclusive bucket offsets
//   [102400,102528) wsum  u32[32]
//   [102528,102688) sc_val f32[40]
//   [102688,102848) sc_idx i32[40]
// Total 102848 B -> two CTAs per SM with regs <= 32.
// ---------------------------------------------------------------------------
#define SMEM_BYTES 102848

__global__ void __launch_bounds__(NT, 2)
pg_sort_kernel(const float* __restrict__ in, float* __restrict__ out,
               int B, int write_indices) {
    extern __shared__ unsigned char smem_raw[];
    unsigned int*   keys  = (unsigned int*)smem_raw;
    unsigned short* idx16 = (unsigned short*)(smem_raw + 32768);
    unsigned short* sidx  = (unsigned short*)(smem_raw + 49152);
    unsigned short* tab13 = (unsigned short*)(smem_raw + 49152);  // alias
    unsigned char* whist = (unsigned char*)(smem_raw + 65536);
    unsigned int* base = (unsigned int*)(smem_raw + 98304);
    unsigned int* wsum = (unsigned int*)(smem_raw + 102400);
    float* sc_val = (float*)(smem_raw + 102528);
    int*   sc_idx = (int*)  (smem_raw + 102688);

    int row = blockIdx.x;
    int tid = threadIdx.x;
    int lane = tid & 31;
    int wid = tid >> 5;
    const float* rowp = in + (size_t)row * N_COLS;
    const float4* rowp4 = (const float4*)rowp;

    // zero per-warp histograms (32KB) + copy bucket table into smem (16KB)
    {
        uint4* whist128 = (uint4*)whist;
        uint4 z4 = make_uint4(0, 0, 0, 0);
        whist128[tid] = z4;
        whist128[tid + NT] = z4;
        unsigned int* tsrc = (unsigned int*)g_tab13;
        unsigned int* tdst = (unsigned int*)tab13;
#pragma unroll
        for (int j = 0; j < 4; j++) tdst[tid + j * NT] = tsrc[tid + j * NT];
    }
    __syncthreads();

    // ---- Phase 1: match-based per-warp ranking (keys recomputed later)
    unsigned int bk[8];                      // packed (bucket<<8)|warp_rank
    {
        float4 v0 = rowp4[tid];
        float4 v1 = rowp4[tid + NT];
        float vv[8] = {v0.x, v0.y, v0.z, v0.w, v1.x, v1.y, v1.z, v1.w};
        unsigned char* wh = whist + wid * NB;
        unsigned int ltmask = (1u << lane) - 1u;
#pragma unroll
        for (int k = 0; k < 8; k++) {
            unsigned int dk = desc_key(vv[k]);
            unsigned int e = (unsigned int)tab13[dk >> 19];
            unsigned int b = (e >> 5) + (((dk & 0x7FFFFu) * (e & 31u)) >> 19);
            unsigned int mask = __match_any_sync(0xFFFFFFFFu, b);
            int leader = __ffs(mask) - 1;
            unsigned int before = 0;
            if (lane == leader) {
                before = (unsigned int)wh[b];
                wh[b] = (unsigned char)(before + (unsigned int)__popc(mask));
            }
            before = __shfl_sync(0xFFFFFFFFu, before, leader);
            unsigned int r = before + (unsigned int)__popc(mask & ltmask);
            bk[k] = (b << 8) | r;
            __syncwarp();
        }
    }
    __syncthreads();

    // ---- Phase 2: cross-warp exclusive offsets (1 bucket per thread)
    {
        unsigned int c[NWARP];
#pragma unroll
        for (int w = 0; w < NWARP; w++) c[w] = (unsigned int)whist[w * NB + tid];
        unsigned int run = 0;
#pragma unroll
        for (int w = 0; w < NWARP; w++) {
            whist[w * NB + tid] = (unsigned char)run;  // per-warp exclusive
            run += c[w];
        }
        unsigned int cnt = run;
        unsigned int inc = cnt;
#pragma unroll
        for (int d = 1; d < 32; d <<= 1) {
            unsigned int v = __shfl_up_sync(0xFFFFFFFFu, inc, d);
            if (lane >= d) inc += v;
        }
        if (lane == 31) wsum[wid] = inc;
        __syncthreads();
        if (tid < 32) {
            unsigned int w = wsum[tid];
            unsigned int wi = w;
#pragma unroll
            for (int d = 1; d < 32; d <<= 1) {
                unsigned int v = __shfl_up_sync(0xFFFFFFFFu, wi, d);
                if (tid >= d) wi += v;
            }
            wsum[tid] = wi - w;   // exclusive warp offsets
        }
        __syncthreads();
        base[tid] = inc - cnt + wsum[wid];
    }
    __syncthreads();   // table reads done; keys/idx16/sidx may be overwritten

    // ---- Phase 3: scatter keys+indices to exact positions
    {
        float4 v0 = rowp4[tid];
        float4 v1 = rowp4[tid + NT];
        float vv[8] = {v0.x, v0.y, v0.z, v0.w, v1.x, v1.y, v1.z, v1.w};
#pragma unroll
        for (int k = 0; k < 8; k++) {
            unsigned int dk = desc_key(vv[k]);
            unsigned int b = bk[k] >> 8;
            unsigned int r = bk[k] & 0xFFu;
            unsigned int pos = base[b] + (unsigned int)whist[wid * NB + b] + r;
            unsigned int idx = (k < 4) ? (4u * tid + k) : (4u * (tid + NT) + (k - 4));
            keys[pos] = dk;
            idx16[pos] = (unsigned short)idx;
            bk[k] = (b << 13) | pos;          // repack for phase 4
        }
    }
    __syncthreads();

    // ---- Phase 4: exact rank by counting within bucket (independent loads)
#pragma unroll
    for (int k = 0; k < 8; k++) {
        unsigned int b = bk[k] >> 13;
        unsigned int pos = bk[k] & 0x1FFFu;
        int start = (int)base[b];
        int end = (b < NB - 1) ? (int)base[b + 1] : N_COLS;
        unsigned int dk = keys[pos];
        unsigned short myidx = idx16[pos];
        unsigned int cnt = 0;
        for (int j = start; j < end; j++) {
            unsigned int kj = keys[j];
            cnt += (kj < dk) ? 1u : 0u;
            if (kj == dk) cnt += (idx16[j] < myidx) ? 1u : 0u;  // exact ties; self false
        }
        sidx[start + cnt] = myidx;
    }
    __syncthreads();

    // ---- Phase 5: outputs
    if (write_indices) {
        float4* oidx4 = (float4*)(out + (size_t)B * N_COLS + (size_t)row * N_COLS);
        const uint2* s2 = (const uint2*)sidx;
#pragma unroll
        for (int g = 0; g < 2; g++) {
            uint2 a = s2[2 * tid + g];        // 4 u16 indices
            float4 f;
            f.x = (float)(a.x & 0xFFFFu);
            f.y = (float)(a.x >> 16);
            f.z = (float)(a.y & 0xFFFFu);
            f.w = (float)(a.y >> 16);
            oidx4[2 * tid + g] = f;
        }
    }

    float* ow = out + (size_t)row * N_COLS;
    float4* ow4 = (float4*)ow;
    float4 z = make_float4(0.f, 0.f, 0.f, 0.f);
    ow4[tid] = z;
    ow4[tid + NT] = z;

    // gather top/bot 20 (value via tiny global gather; idx from sidx)
    if (tid < 40) {
        int rnk = (tid < 20) ? tid : (N_COLS - 20 + (tid - 20));
        int idx = (int)sidx[rnk];
        sc_idx[tid] = idx;
        float x = rowp[idx];
        sc_val[tid] = (tid < 20) ? x : -x;
    }
    __syncthreads();  // orders the zero-fill stores before the scatter below

    if (tid < 40) {
        int g0 = (tid < 20) ? 0 : 20;
        float m = -1e30f;
#pragma unroll
        for (int j = 0; j < 20; j++) m = fmaxf(m, sc_val[g0 + j]);
        float s = 0.f;
#pragma unroll
        for (int j = 0; j < 20; j++) s += expf(sc_val[g0 + j] - m);
        float w = expf(sc_val[tid] - m) / s;
        ow[sc_idx[tid]] = (tid < 20) ? w : -w;
    }
}

extern "C" void kernel_launch(void* const* d_in, const int* in_sizes, int n_in,
                              void* d_out, int out_size) {
    const float* in = (const float*)d_in[0];
    float* out = (float*)d_out;
    int total = in_sizes[0];
    int B = total / N_COLS;
    int write_indices = (out_size >= 2 * total) ? 1 : 0;

    cudaFuncSetAttribute(pg_sort_kernel,
                         cudaFuncAttributeMaxDynamicSharedMemorySize, SMEM_BYTES);

    pg_build13<<<1, NT>>>();
    pg_sort_kernel<<<B, NT, SMEM_BYTES>>>(in, out, B, write_indices);
}

// round 10
// speedup vs baseline: 1.1647x; 1.1647x over previous
#include <cuda_runtime.h>
#include <stdint.h>

// Problem: B x N fp32 scores. Outputs (concatenated into float d_out):
//   [0, B*N)      portfolio_weights (sparse +softmax(top20), -softmax(bot20))
//   [B*N, 2*B*N)  sorted_indices of argsort(-scores) as float
#define N_COLS 8192
#define NB     1024   // bucket id space (used ids <= 1000)
#define NT     1024   // threads per CTA (one CTA per row)
#define NWARP  32
#define KBUCK  1000   // equal-probability bucket budget

// 13-bit-prefix bucket table. For prefix p = dk >> 19:
//   entry = (base << 5) | cells   (base <= 1000 fits 11 bits, cells <= 31)
//   bucket = base + ((dk & 0x7FFFF) * cells) >> 19
__device__ unsigned short g_tab13[8192];

__device__ __forceinline__ float key_to_val(unsigned int dk) {
    unsigned int ukey = ~dk;
    return (ukey & 0x80000000u) ? __uint_as_float(ukey ^ 0x80000000u)
                                : __uint_as_float(~ukey);
}

__device__ __forceinline__ unsigned int desc_key(float x) {
    unsigned int u = __float_as_uint(x);
    unsigned int ukey = (u & 0x80000000u) ? ~u : (u | 0x80000000u);
    return ~ukey;   // ascending key == descending value
}

// Build table in ONE kernel (1 block x 1024 threads).
__global__ void pg_build13() {
    __shared__ unsigned int tmax[NT];
    __shared__ unsigned int fixed[8193];
    int t = threadIdx.x;
    unsigned int v[8];
    unsigned int cm = 0;
#pragma unroll
    for (int i = 0; i < 8; i++) {
        int p = t * 8 + i;
        float x = key_to_val(((unsigned int)p) << 19);
        float F;
        if (!(x == x)) F = (p < 4096) ? 0.f : 1.f;            // NaN prefixes
        else           F = normcdff(-fminf(fmaxf(x, -30.f), 30.f)); // 1-Phi(x)
        int b = (int)floorf(F * (float)KBUCK);
        b = b < 0 ? 0 : (b > KBUCK ? KBUCK : b);
        v[i] = (unsigned int)b;
        cm = max(cm, v[i]);
    }
    tmax[t] = cm;
    __syncthreads();
    for (int d = 1; d < NT; d <<= 1) {
        unsigned int w = (t >= d) ? tmax[t - d] : 0u;
        __syncthreads();
        if (t >= d) tmax[t] = max(tmax[t], w);
        __syncthreads();
    }
    unsigned int run = (t == 0) ? 0u : tmax[t - 1];
#pragma unroll
    for (int i = 0; i < 8; i++) {
        run = max(run, v[i]);
        fixed[t * 8 + i] = run;
    }
    if (t == 0) fixed[8192] = KBUCK;
    __syncthreads();
    for (int p = t; p < 8192; p += NT) {
        unsigned int b0 = fixed[p];
        unsigned int c = fixed[p + 1] - b0;
        if (c > 31u) c = 31u;
        g_tab13[p] = (unsigned short)((b0 << 5) | c);
    }
}

// ---------------------------------------------------------------------------
// SMEM layout (bytes):
//   [0,     65536)  data  u64[8192]  packed (dk<<32)|idx, bucket-grouped (ph3+)
//                   ALIAS [0,16384): tab13 u16[8192]  (phases 0-1 only)
//   [65536, 98304)  whist u8[32][1024] per-warp counts -> exclusive offs (ph1-3)
//                   ALIAS [65536,81920): sidx u16[8192] rank->index (ph4+)
//   [98304,102400)  base  u32[1024]  global exclusive bucket offsets
//   [102400,102528) wsum  u32[32]
//   [102528,102688) sc_val f32[40]
//   [102688,102848) sc_idx i32[40]
// Total 102848 B -> two CTAs per SM with regs <= 32.
// ---------------------------------------------------------------------------
#define SMEM_BYTES 102848

__global__ void __launch_bounds__(NT, 2)
pg_sort_kernel(const float* __restrict__ in, float* __restrict__ out,
               int B, int write_indices) {
    extern __shared__ unsigned char smem_raw[];
    unsigned long long* data = (unsigned long long*)smem_raw;
    unsigned short* tab13 = (unsigned short*)smem_raw;            // alias ph0-1
    unsigned char* whist = (unsigned char*)(smem_raw + 65536);
    unsigned short* sidx = (unsigned short*)(smem_raw + 65536);   // alias ph4+
    unsigned int* base = (unsigned int*)(smem_raw + 98304);
    unsigned int* wsum = (unsigned int*)(smem_raw + 102400);
    float* sc_val = (float*)(smem_raw + 102528);
    int*   sc_idx = (int*)  (smem_raw + 102688);

    int row = blockIdx.x;
    int tid = threadIdx.x;
    int lane = tid & 31;
    int wid = tid >> 5;
    const float* rowp = in + (size_t)row * N_COLS;
    const float4* rowp4 = (const float4*)rowp;

    // Phase 0: zero per-warp histograms (32KB) + copy table into smem (16KB)
    {
        uint4* whist128 = (uint4*)whist;
        uint4 z4 = make_uint4(0, 0, 0, 0);
        whist128[tid] = z4;
        whist128[tid + NT] = z4;
        unsigned int* tsrc = (unsigned int*)g_tab13;
        unsigned int* tdst = (unsigned int*)tab13;
#pragma unroll
        for (int j = 0; j < 4; j++) tdst[tid + j * NT] = tsrc[tid + j * NT];
    }
    __syncthreads();

    // ---- Phase 1: branchless match-based per-warp ranking.
    // Lanes sharing a bucket read the same counter (broadcast) and store the
    // IDENTICAL updated value -> race-free without a leader branch.
    unsigned int bk[8];                      // packed (bucket<<8)|warp_rank
    {
        float4 v0 = rowp4[tid];
        float4 v1 = rowp4[tid + NT];
        float vv[8] = {v0.x, v0.y, v0.z, v0.w, v1.x, v1.y, v1.z, v1.w};
        unsigned char* wh = whist + wid * NB;
        unsigned int ltmask = (1u << lane) - 1u;
#pragma unroll
        for (int k = 0; k < 8; k++) {
            unsigned int dk = desc_key(vv[k]);
            unsigned int e = (unsigned int)tab13[dk >> 19];
            unsigned int b = (e >> 5) + (((dk & 0x7FFFFu) * (e & 31u)) >> 19);
            unsigned int mask = __match_any_sync(0xFFFFFFFFu, b);
            unsigned int before = (unsigned int)wh[b];                 // all lanes
            wh[b] = (unsigned char)(before + (unsigned int)__popc(mask)); // same value
            bk[k] = (b << 8) | (before + (unsigned int)__popc(mask & ltmask));
            __syncwarp();
        }
    }
    __syncthreads();

    // ---- Phase 2: cross-warp exclusive offsets (1 bucket per thread)
    {
        unsigned int c[NWARP];
#pragma unroll
        for (int w = 0; w < NWARP; w++) c[w] = (unsigned int)whist[w * NB + tid];
        unsigned int run = 0;
#pragma unroll
        for (int w = 0; w < NWARP; w++) {
            whist[w * NB + tid] = (unsigned char)run;  // per-warp exclusive
            run += c[w];
        }
        unsigned int cnt = run;
        unsigned int inc = cnt;
#pragma unroll
        for (int d = 1; d < 32; d <<= 1) {
            unsigned int v = __shfl_up_sync(0xFFFFFFFFu, inc, d);
            if (lane >= d) inc += v;
        }
        if (lane == 31) wsum[wid] = inc;
        __syncthreads();
        if (tid < 32) {
            unsigned int w = wsum[tid];
            unsigned int wi = w;
#pragma unroll
            for (int d = 1; d < 32; d <<= 1) {
                unsigned int v = __shfl_up_sync(0xFFFFFFFFu, wi, d);
                if (tid >= d) wi += v;
            }
            wsum[tid] = wi - w;   // exclusive warp offsets
        }
        __syncthreads();
        base[tid] = inc - cnt + wsum[wid];
    }
    __syncthreads();   // table reads done; data[] may now be overwritten

    // ---- Phase 3: scatter packed (dk<<32)|idx to exact positions
    {
        float4 v0 = rowp4[tid];
        float4 v1 = rowp4[tid + NT];
        float vv[8] = {v0.x, v0.y, v0.z, v0.w, v1.x, v1.y, v1.z, v1.w};
#pragma unroll
        for (int k = 0; k < 8; k++) {
            unsigned int dk = desc_key(vv[k]);
            unsigned int b = bk[k] >> 8;
            unsigned int r = bk[k] & 0xFFu;
            unsigned int pos = base[b] + (unsigned int)whist[wid * NB + b] + r;
            unsigned int idx = (k < 4) ? (4u * tid + k) : (4u * (tid + NT) + (k - 4));
            data[pos] = ((unsigned long long)dk << 32) | idx;
            bk[k] = (b << 13) | pos;          // repack for phase 4
        }
    }
    __syncthreads();   // whist dead; sidx region may now be written

    // ---- Phase 4: branchless exact rank by counting unique u64 entries.
    // Scan the 2-aligned superset of the bucket; neighbor-bucket extras are
    // strictly smaller (left, subtracted) or strictly larger (right, +0).
    {
        const uint4* d4 = (const uint4*)data;
#pragma unroll
        for (int k = 0; k < 8; k++) {
            unsigned int b = bk[k] >> 13;
            unsigned int pos = bk[k] & 0x1FFFu;
            int start = (int)base[b];
            int end = (b < NB - 1) ? (int)base[b + 1] : N_COLS;
            unsigned long long me = data[pos];
            unsigned int mylo = (unsigned int)me;
            unsigned int myhi = (unsigned int)(me >> 32);
            int s2 = start & ~1;
            int e2 = (end + 1) & ~1;
            int cnt = s2 - start;               // subtract left extras
            for (int j = (s2 >> 1); j < (e2 >> 1); j++) {
                uint4 q = d4[j];
                cnt += (int)((q.y < myhi) | ((q.y == myhi) & (q.x < mylo)));
                cnt += (int)((q.w < myhi) | ((q.w == myhi) & (q.z < mylo)));
            }
            sidx[start + cnt] = (unsigned short)mylo;
        }
    }
    __syncthreads();

    // ---- Phase 5: outputs
    if (write_indices) {
        float4* oidx4 = (float4*)(out + (size_t)B * N_COLS + (size_t)row * N_COLS);
        const uint2* s2 = (const uint2*)sidx;
#pragma unroll
        for (int g = 0; g < 2; g++) {
            uint2 a = s2[2 * tid + g];        // 4 u16 indices
            float4 f;
            f.x = (float)(a.x & 0xFFFFu);
            f.y = (float)(a.x >> 16);
            f.z = (float)(a.y & 0xFFFFu);
            f.w = (float)(a.y >> 16);
            oidx4[2 * tid + g] = f;
        }
    }

    float* ow = out + (size_t)row * N_COLS;
    float4* ow4 = (float4*)ow;
    float4 z = make_float4(0.f, 0.f, 0.f, 0.f);
    ow4[tid] = z;
    ow4[tid + NT] = z;

    // gather top/bot 20 (idx from sidx; value via tiny L2 gather)
    if (tid < 40) {
        int rnk = (tid < 20) ? tid : (N_COLS - 20 + (tid - 20));
        int idx = (int)sidx[rnk];
        sc_idx[tid] = idx;
        float x = rowp[idx];
        sc_val[tid] = (tid < 20) ? x : -x;
    }
    __syncthreads();  // orders the zero-fill stores before the scatter below

    if (tid < 40) {
        int g0 = (tid < 20) ? 0 : 20;
        float m = -1e30f;
#pragma unroll
        for (int j = 0; j < 20; j++) m = fmaxf(m, sc_val[g0 + j]);
        float s = 0.f;
#pragma unroll
        for (int j = 0; j < 20; j++) s += expf(sc_val[g0 + j] - m);
        float w = expf(sc_val[tid] - m) / s;
        ow[sc_idx[tid]] = (tid < 20) ? w : -w;
    }
}

extern "C" void kernel_launch(void* const* d_in, const int* in_sizes, int n_in,
                              void* d_out, int out_size) {
    const float* in = (const float*)d_in[0];
    float* out = (float*)d_out;
    int total = in_sizes[0];
    int B = total / N_COLS;
    int write_indices = (out_size >= 2 * total) ? 1 : 0;

    cudaFuncSetAttribute(pg_sort_kernel,
                         cudaFuncAttributeMaxDynamicSharedMemorySize, SMEM_BYTES);

    pg_build13<<<1, NT>>>();
    pg_sort_kernel<<<B, NT, SMEM_BYTES>>>(in, out, B, write_indices);
}

// round 11
// speedup vs baseline: 1.3160x; 1.1299x over previous
#include <cuda_runtime.h>
#include <stdint.h>

// Problem: B x N fp32 scores. Outputs (concatenated into float d_out):
//   [0, B*N)      portfolio_weights (sparse +softmax(top20), -softmax(bot20))
//   [B*N, 2*B*N)  sorted_indices of argsort(-scores) as float
#define N_COLS 8192
#define NB     1024   // bucket id space (used ids <= 1000)
#define NT     1024   // threads per CTA (one CTA per row)
#define NWARP  32
#define KBUCK  1000   // equal-probability bucket budget

// 13-bit-prefix bucket table. For prefix p = dk >> 19:
//   entry = (base << 5) | cells   (base <= 1000 fits 11 bits, cells <= 31)
//   bucket = base + ((dk & 0x7FFFF) * cells) >> 19
__device__ unsigned short g_tab13[8192];

__device__ __forceinline__ float key_to_val(unsigned int dk) {
    unsigned int ukey = ~dk;
    return (ukey & 0x80000000u) ? __uint_as_float(ukey ^ 0x80000000u)
                                : __uint_as_float(~ukey);
}

__device__ __forceinline__ unsigned int desc_key(float x) {
    unsigned int u = __float_as_uint(x);
    unsigned int ukey = (u & 0x80000000u) ? ~u : (u | 0x80000000u);
    return ~ukey;   // ascending key == descending value
}

// Build table in ONE kernel (1 block x 1024 threads).
__global__ void pg_build13() {
    __shared__ unsigned int tmax[NT];
    __shared__ unsigned int fixed[8193];
    int t = threadIdx.x;
    unsigned int v[8];
    unsigned int cm = 0;
#pragma unroll
    for (int i = 0; i < 8; i++) {
        int p = t * 8 + i;
        float x = key_to_val(((unsigned int)p) << 19);
        float F;
        if (!(x == x)) F = (p < 4096) ? 0.f : 1.f;            // NaN prefixes
        else           F = normcdff(-fminf(fmaxf(x, -30.f), 30.f)); // 1-Phi(x)
        int b = (int)floorf(F * (float)KBUCK);
        b = b < 0 ? 0 : (b > KBUCK ? KBUCK : b);
        v[i] = (unsigned int)b;
        cm = max(cm, v[i]);
    }
    tmax[t] = cm;
    __syncthreads();
    for (int d = 1; d < NT; d <<= 1) {
        unsigned int w = (t >= d) ? tmax[t - d] : 0u;
        __syncthreads();
        if (t >= d) tmax[t] = max(tmax[t], w);
        __syncthreads();
    }
    unsigned int run = (t == 0) ? 0u : tmax[t - 1];
#pragma unroll
    for (int i = 0; i < 8; i++) {
        run = max(run, v[i]);
        fixed[t * 8 + i] = run;
    }
    if (t == 0) fixed[8192] = KBUCK;
    __syncthreads();
    for (int p = t; p < 8192; p += NT) {
        unsigned int b0 = fixed[p];
        unsigned int c = fixed[p + 1] - b0;
        if (c > 31u) c = 31u;
        g_tab13[p] = (unsigned short)((b0 << 5) | c);
    }
}

// ---------------------------------------------------------------------------
// Element ownership: warp wid owns global elements [wid*256, wid*256+256);
// thread lane handles idx = wid*256 + k*32 + lane for k = 0..7 (k-major).
// => scatter position order within a bucket (warp, k, lane lexicographic)
//    equals ascending original index, so ties break exactly by position.
//
// SMEM layout (bytes):
//   [0,     32768)  keys u32[8192]  scattered keys, bucket-grouped (ph3+)
//   [32768, 49152)  sidx u16[8192]  rank->index (ph4+)
//                   ALIAS: tab13 u16[8192] bucket table (ph0-1 only)
//   [49152, 81920)  whist u8[32][1024] per-warp counts -> excl offs (ph1-3)
//   [81920, 86016)  base u32[1024]  global exclusive bucket offsets
//   [86016, 86144)  wsum u32[32]
//   [86144, 86304)  sc_val f32[40]
//   [86304, 86464)  sc_idx i32[40]
// Total 86464 B -> two CTAs per SM with regs <= 32; ~55KB left as real L1.
// ---------------------------------------------------------------------------
#define SMEM_BYTES 86464

__global__ void __launch_bounds__(NT, 2)
pg_sort_kernel(const float* __restrict__ in, float* __restrict__ out,
               int B, int write_indices) {
    extern __shared__ unsigned char smem_raw[];
    unsigned int*   keys  = (unsigned int*)smem_raw;
    unsigned short* sidx  = (unsigned short*)(smem_raw + 32768);
    unsigned short* tab13 = (unsigned short*)(smem_raw + 32768);  // alias ph0-1
    unsigned char*  whist = (unsigned char*)(smem_raw + 49152);
    unsigned int*   base  = (unsigned int*)(smem_raw + 81920);
    unsigned int*   wsum  = (unsigned int*)(smem_raw + 86016);
    float* sc_val = (float*)(smem_raw + 86144);
    int*   sc_idx = (int*)  (smem_raw + 86304);

    int row = blockIdx.x;
    int tid = threadIdx.x;
    int lane = tid & 31;
    int wid = tid >> 5;
    const float* rowp = in + (size_t)row * N_COLS;

    // Phase 0: zero per-warp histograms (32KB) + copy table to smem (16KB)
    {
        uint4* wz = (uint4*)whist;
        uint4 z4 = make_uint4(0, 0, 0, 0);
        wz[tid] = z4;
        wz[tid + NT] = z4;
        unsigned int* tsrc = (unsigned int*)g_tab13;
        unsigned int* tdst = (unsigned int*)tab13;
#pragma unroll
        for (int j = 0; j < 4; j++) tdst[tid + j * NT] = tsrc[tid + j * NT];
    }
    __syncthreads();

    // ---- Phase 1: branchless match-based per-warp ranking (k-major layout)
    unsigned int dk[8];
    unsigned int bk[8];                      // packed (bucket<<8)|warp_rank
    {
        int ebase = wid * 256 + lane;
        float vv[8];
#pragma unroll
        for (int k = 0; k < 8; k++) vv[k] = rowp[ebase + k * 32];  // MLP=8
        unsigned char* wh = whist + wid * NB;
        unsigned int ltmask = (1u << lane) - 1u;
#pragma unroll
        for (int k = 0; k < 8; k++) {
            unsigned int d = desc_key(vv[k]);
            dk[k] = d;
            unsigned int e = (unsigned int)tab13[d >> 19];
            unsigned int b = (e >> 5) + (((d & 0x7FFFFu) * (e & 31u)) >> 19);
            unsigned int mask = __match_any_sync(0xFFFFFFFFu, b);
            unsigned int before = (unsigned int)wh[b];                 // all lanes
            wh[b] = (unsigned char)(before + (unsigned int)__popc(mask)); // same val
            bk[k] = (b << 8) | (before + (unsigned int)__popc(mask & ltmask));
            __syncwarp();
        }
    }
    __syncthreads();

    // ---- Phase 2: cross-warp exclusive offsets (1 bucket per thread, fused)
    {
        unsigned int run = 0;
#pragma unroll
        for (int w = 0; w < NWARP; w++) {
            unsigned int cc = (unsigned int)whist[w * NB + tid];
            whist[w * NB + tid] = (unsigned char)run;  // per-warp exclusive
            run += cc;
        }
        unsigned int cnt = run;
        unsigned int inc = cnt;
#pragma unroll
        for (int d = 1; d < 32; d <<= 1) {
            unsigned int v = __shfl_up_sync(0xFFFFFFFFu, inc, d);
            if (lane >= d) inc += v;
        }
        if (lane == 31) wsum[wid] = inc;
        __syncthreads();
        if (tid < 32) {
            unsigned int w = wsum[tid];
            unsigned int wi = w;
#pragma unroll
            for (int d = 1; d < 32; d <<= 1) {
                unsigned int v = __shfl_up_sync(0xFFFFFFFFu, wi, d);
                if (tid >= d) wi += v;
            }
            wsum[tid] = wi - w;   // exclusive warp offsets
        }
        __syncthreads();
        base[tid] = inc - cnt + wsum[wid];
    }
    __syncthreads();   // table reads done; keys[] may now be overwritten

    // ---- Phase 3: scatter keys to exact positions
    {
#pragma unroll
        for (int k = 0; k < 8; k++) {
            unsigned int b = bk[k] >> 8;
            unsigned int r = bk[k] & 0xFFu;
            unsigned int pos = base[b] + (unsigned int)whist[wid * NB + b] + r;
            keys[pos] = dk[k];
            bk[k] = (b << 13) | pos;          // repack for phase 4
        }
    }
    __syncthreads();   // whist dead; sidx region may now be written

    // ---- Phase 4: branchless rank by counting u32 keys (vectorized).
    // Left extras (< start) are strictly smaller (pre-subtracted); right
    // extras (>= end) strictly larger. eq counts equals incl. self; eq==1
    // means no tie. Rare tie path counts equals at positions < pos, which
    // by construction equals "equal keys with smaller original index".
    {
        const uint4* k4 = (const uint4*)keys;
#pragma unroll
        for (int k = 0; k < 8; k++) {
            unsigned int b = bk[k] >> 13;
            int pos = (int)(bk[k] & 0x1FFFu);
            int start = (int)base[b];
            int end = (b < NB - 1) ? (int)base[b + 1] : N_COLS;
            unsigned int mydk = dk[k];
            int s4 = start >> 2;
            int e4 = (end + 3) >> 2;
            int lt = (s4 << 2) - start;
            int eq = 0;
            for (int j = s4; j < e4; j++) {
                uint4 q = k4[j];
                lt += (int)(q.x < mydk) + (int)(q.y < mydk)
                    + (int)(q.z < mydk) + (int)(q.w < mydk);
                eq += (int)(q.x == mydk) + (int)(q.y == mydk)
                    + (int)(q.z == mydk) + (int)(q.w == mydk);
            }
            int rank = lt;
            if (eq != 1) {                    // rare: exact stable tie-break
                for (int j = start; j < pos; j++)
                    rank += (int)(keys[j] == mydk);
            }
            sidx[start + rank] = (unsigned short)(wid * 256 + k * 32 + lane);
        }
    }
    __syncthreads();

    // ---- Phase 5: outputs
    if (write_indices) {
        float4* oidx4 = (float4*)(out + (size_t)B * N_COLS + (size_t)row * N_COLS);
        const uint2* s2 = (const uint2*)sidx;
#pragma unroll
        for (int g = 0; g < 2; g++) {
            uint2 a = s2[2 * tid + g];        // 4 u16 indices
            float4 f;
            f.x = (float)(a.x & 0xFFFFu);
            f.y = (float)(a.x >> 16);
            f.z = (float)(a.y & 0xFFFFu);
            f.w = (float)(a.y >> 16);
            oidx4[2 * tid + g] = f;
        }
    }

    float* ow = out + (size_t)row * N_COLS;
    float4* ow4 = (float4*)ow;
    float4 z = make_float4(0.f, 0.f, 0.f, 0.f);
    ow4[tid] = z;
    ow4[tid + NT] = z;

    // gather top/bot 20 (idx from sidx; value via tiny L2 gather)
    if (tid < 40) {
        int rnk = (tid < 20) ? tid : (N_COLS - 20 + (tid - 20));
        int idx = (int)sidx[rnk];
        sc_idx[tid] = idx;
        float x = rowp[idx];
        sc_val[tid] = (tid < 20) ? x : -x;
    }
    __syncthreads();  // orders the zero-fill stores before the scatter below

    if (tid < 40) {
        int g0 = (tid < 20) ? 0 : 20;
        float m = -1e30f;
#pragma unroll
        for (int j = 0; j < 20; j++) m = fmaxf(m, sc_val[g0 + j]);
        float s = 0.f;
#pragma unroll
        for (int j = 0; j < 20; j++) s += expf(sc_val[g0 + j] - m);
        float w = expf(sc_val[tid] - m) / s;
        ow[sc_idx[tid]] = (tid < 20) ? w : -w;
    }
}

extern "C" void kernel_launch(void* const* d_in, const int* in_sizes, int n_in,
                              void* d_out, int out_size) {
    const float* in = (const float*)d_in[0];
    float* out = (float*)d_out;
    int total = in_sizes[0];
    int B = total / N_COLS;
    int write_indices = (out_size >= 2 * total) ? 1 : 0;

    cudaFuncSetAttribute(pg_sort_kernel,
                         cudaFuncAttributeMaxDynamicSharedMemorySize, SMEM_BYTES);

    pg_build13<<<1, NT>>>();
    pg_sort_kernel<<<B, NT, SMEM_BYTES>>>(in, out, B, write_indices);
}

// round 12
// speedup vs baseline: 1.3317x; 1.0119x over previous
#include <cuda_runtime.h>
#include <stdint.h>

// Problem: B x N fp32 scores. Outputs (concatenated into float d_out):
//   [0, B*N)      portfolio_weights (sparse +softmax(top20), -softmax(bot20))
//   [B*N, 2*B*N)  sorted_indices of argsort(-scores) as float
#define N_COLS 8192
#define NB     1536   // bucket id space (used ids <= 1500)
#define NT     1024   // threads per CTA (one CTA per row)
#define NWARP  32
#define KBUCK  1500   // equal-probability bucket budget (avg ~5.5/bucket)

// 13-bit-prefix bucket table. For prefix p = dk >> 19:
//   entry = (base << 5) | cells   (base <= 1500 fits 11 bits, cells <= 31)
//   bucket = base + ((dk & 0x7FFFF) * cells) >> 19
__device__ unsigned short g_tab13[8192];

__device__ __forceinline__ float key_to_val(unsigned int dk) {
    unsigned int ukey = ~dk;
    return (ukey & 0x80000000u) ? __uint_as_float(ukey ^ 0x80000000u)
                                : __uint_as_float(~ukey);
}

__device__ __forceinline__ unsigned int desc_key(float x) {
    unsigned int u = __float_as_uint(x);
    unsigned int ukey = (u & 0x80000000u) ? ~u : (u | 0x80000000u);
    return ~ukey;   // ascending key == descending value
}

// Build table in ONE kernel (1 block x 1024 threads).
__global__ void pg_build13() {
    __shared__ unsigned int tmax[NT];
    __shared__ unsigned int fixed[8193];
    int t = threadIdx.x;
    unsigned int v[8];
    unsigned int cm = 0;
#pragma unroll
    for (int i = 0; i < 8; i++) {
        int p = t * 8 + i;
        float x = key_to_val(((unsigned int)p) << 19);
        float F;
        if (!(x == x)) F = (p < 4096) ? 0.f : 1.f;            // NaN prefixes
        else           F = normcdff(-fminf(fmaxf(x, -30.f), 30.f)); // 1-Phi(x)
        int b = (int)floorf(F * (float)KBUCK);
        b = b < 0 ? 0 : (b > KBUCK ? KBUCK : b);
        v[i] = (unsigned int)b;
        cm = max(cm, v[i]);
    }
    tmax[t] = cm;
    __syncthreads();
    for (int d = 1; d < NT; d <<= 1) {
        unsigned int w = (t >= d) ? tmax[t - d] : 0u;
        __syncthreads();
        if (t >= d) tmax[t] = max(tmax[t], w);
        __syncthreads();
    }
    unsigned int run = (t == 0) ? 0u : tmax[t - 1];
#pragma unroll
    for (int i = 0; i < 8; i++) {
        run = max(run, v[i]);
        fixed[t * 8 + i] = run;
    }
    if (t == 0) fixed[8192] = KBUCK;
    __syncthreads();
    for (int p = t; p < 8192; p += NT) {
        unsigned int b0 = fixed[p];
        unsigned int c = fixed[p + 1] - b0;
        if (c > 31u) c = 31u;
        g_tab13[p] = (unsigned short)((b0 << 5) | c);
    }
}

// ---------------------------------------------------------------------------
// Element ownership: warp wid owns elements [wid*256, wid*256+256);
// lane handles idx = wid*256 + k*32 + lane (k-major) so scatter position
// order within a bucket equals ascending original index (exact stable ties).
//
// SMEM layout (bytes):
//   [0,     32768)  keys u32[8192]   scattered keys, bucket-grouped (ph3+)
//   [32768, 49152)  sidx u16[8192]   rank->index (ph4+)
//                   ALIAS: tab13 u16[8192] bucket table (ph0-1 only)
//   [49152, 98304)  whist u8[32][1536] per-warp counts -> excl offs (ph1-3)
//   [98304,104452)  base u32[1537]   global excl bucket offsets + sentinel
//   [104464,104720) wsum u32[64]     scan staging (A warps, B warps, total)
//   [104720,104880) sc_val f32[40]
//   [104880,105040) sc_idx i32[40]
// Total 105040 B -> two CTAs per SM (210080 <= 228KB) with regs <= 32.
// ---------------------------------------------------------------------------
#define SMEM_BYTES 105040

__global__ void __launch_bounds__(NT, 2)
pg_sort_kernel(const float* __restrict__ in, float* __restrict__ out,
               int B, int write_indices) {
    extern __shared__ unsigned char smem_raw[];
    unsigned int*   keys  = (unsigned int*)smem_raw;
    unsigned short* sidx  = (unsigned short*)(smem_raw + 32768);
    unsigned short* tab13 = (unsigned short*)(smem_raw + 32768);  // alias ph0-1
    unsigned char*  whist = (unsigned char*)(smem_raw + 49152);
    unsigned int*   base  = (unsigned int*)(smem_raw + 98304);
    unsigned int*   wsum  = (unsigned int*)(smem_raw + 104464);
    float* sc_val = (float*)(smem_raw + 104720);
    int*   sc_idx = (int*)  (smem_raw + 104880);

    int row = blockIdx.x;
    int tid = threadIdx.x;
    int lane = tid & 31;
    int wid = tid >> 5;
    const float* rowp = in + (size_t)row * N_COLS;

    // Phase 0: zero per-warp histograms (48KB) + copy table to smem (16KB)
    {
        uint4* wz = (uint4*)whist;
        uint4 z4 = make_uint4(0, 0, 0, 0);
        wz[tid] = z4;
        wz[tid + NT] = z4;
        wz[tid + 2 * NT] = z4;
        unsigned int* tsrc = (unsigned int*)g_tab13;
        unsigned int* tdst = (unsigned int*)tab13;
#pragma unroll
        for (int j = 0; j < 4; j++) tdst[tid + j * NT] = tsrc[tid + j * NT];
    }
    __syncthreads();

    // ---- Phase 1: branchless match-based per-warp ranking (k-major layout)
    unsigned int dk[8];
    unsigned int bk[8];                      // packed (bucket<<8)|warp_rank
    {
        int ebase = wid * 256 + lane;
        float vv[8];
#pragma unroll
        for (int k = 0; k < 8; k++) vv[k] = rowp[ebase + k * 32];  // MLP=8
        unsigned char* wh = whist + wid * NB;
        unsigned int ltmask = (1u << lane) - 1u;
#pragma unroll
        for (int k = 0; k < 8; k++) {
            unsigned int d = desc_key(vv[k]);
            dk[k] = d;
            unsigned int e = (unsigned int)tab13[d >> 19];
            unsigned int b = (e >> 5) + (((d & 0x7FFFFu) * (e & 31u)) >> 19);
            unsigned int mask = __match_any_sync(0xFFFFFFFFu, b);
            unsigned int before = (unsigned int)wh[b];                 // all lanes
            wh[b] = (unsigned char)(before + (unsigned int)__popc(mask)); // same val
            bk[k] = (b << 8) | (before + (unsigned int)__popc(mask & ltmask));
            __syncwarp();
        }
    }
    __syncthreads();

    // ---- Phase 2: cross-warp exclusive offsets over 1536 buckets.
    // Thread t owns bucket t; threads 0..511 also own bucket 1024+t.
    {
        unsigned int run0 = 0;
#pragma unroll
        for (int w = 0; w < NWARP; w++) {
            unsigned int cc = (unsigned int)whist[w * NB + tid];
            whist[w * NB + tid] = (unsigned char)run0;
            run0 += cc;
        }
        unsigned int cnt1 = 0;
        if (tid < 512) {
            unsigned int run1 = 0;
#pragma unroll
            for (int w = 0; w < NWARP; w++) {
                unsigned int cc = (unsigned int)whist[w * NB + 1024 + tid];
                whist[w * NB + 1024 + tid] = (unsigned char)run1;
                run1 += cc;
            }
            cnt1 = run1;
        }
        // warp-inclusive scans
        unsigned int incA = run0;
#pragma unroll
        for (int d = 1; d < 32; d <<= 1) {
            unsigned int v = __shfl_up_sync(0xFFFFFFFFu, incA, d);
            if (lane >= d) incA += v;
        }
        if (lane == 31) wsum[wid] = incA;
        unsigned int incB = cnt1;
        if (tid < 512) {
#pragma unroll
            for (int d = 1; d < 32; d <<= 1) {
                unsigned int v = __shfl_up_sync(0xFFFFFFFFu, incB, d);
                if (lane >= d) incB += v;
            }
            if (lane == 31) wsum[32 + wid] = incB;
        }
        __syncthreads();
        if (tid < 32) {                       // combine A (warp 0)
            unsigned int w = wsum[tid];
            unsigned int wi = w;
#pragma unroll
            for (int d = 1; d < 32; d <<= 1) {
                unsigned int v = __shfl_up_sync(0xFFFFFFFFu, wi, d);
                if (tid >= d) wi += v;
            }
            if (tid == 31) wsum[48] = wi;     // grand total of A
            wsum[tid] = wi - w;
        } else if (tid >= 32 && tid < 48) {   // combine B (warp 1, lanes 0-15)
            int l = tid - 32;
            unsigned int w = wsum[32 + l];
            unsigned int wi = w;
#pragma unroll
            for (int d = 1; d < 16; d <<= 1) {
                unsigned int v = __shfl_up_sync(0x0000FFFFu, wi, d);
                if (l >= d) wi += v;
            }
            wsum[32 + l] = wi - w;
        }
        __syncthreads();
        base[tid] = incA - run0 + wsum[wid];
        if (tid < 512) base[1024 + tid] = wsum[48] + incB - cnt1 + wsum[32 + wid];
        if (tid == 0) base[1536] = N_COLS;    // sentinel
    }
    __syncthreads();   // table reads done; keys[] may now be overwritten

    // ---- Phase 3: scatter keys to exact positions
    {
#pragma unroll
        for (int k = 0; k < 8; k++) {
            unsigned int b = bk[k] >> 8;
            unsigned int r = bk[k] & 0xFFu;
            unsigned int pos = base[b] + (unsigned int)whist[wid * NB + b] + r;
            keys[pos] = dk[k];
            bk[k] = (b << 13) | pos;          // repack (b<=1535:11b, pos:13b)
        }
    }
    __syncthreads();   // whist dead; sidx region may now be written

    // ---- Phase 4: branchless rank by counting u32 keys (vectorized).
    {
        const uint4* k4 = (const uint4*)keys;
#pragma unroll
        for (int k = 0; k < 8; k++) {
            unsigned int b = bk[k] >> 13;
            int pos = (int)(bk[k] & 0x1FFFu);
            int start = (int)base[b];
            int end = (int)base[b + 1];       // sentinel makes this safe
            unsigned int mydk = dk[k];
            int s4 = start >> 2;
            int e4 = (end + 3) >> 2;
            int lt = (s4 << 2) - start;
            int eq = 0;
            for (int j = s4; j < e4; j++) {
                uint4 q = k4[j];
                lt += (int)(q.x < mydk) + (int)(q.y < mydk)
                    + (int)(q.z < mydk) + (int)(q.w < mydk);
                eq += (int)(q.x == mydk) + (int)(q.y == mydk)
                    + (int)(q.z == mydk) + (int)(q.w == mydk);
            }
            int rank = lt;
            if (eq != 1) {                    // rare: exact stable tie-break
                for (int j = start; j < pos; j++)
                    rank += (int)(keys[j] == mydk);
            }
            sidx[start + rank] = (unsigned short)(wid * 256 + k * 32 + lane);
        }
    }
    __syncthreads();

    // ---- Phase 5: outputs
    if (write_indices) {
        float4* oidx4 = (float4*)(out + (size_t)B * N_COLS + (size_t)row * N_COLS);
        const uint2* s2 = (const uint2*)sidx;
#pragma unroll
        for (int g = 0; g < 2; g++) {
            uint2 a = s2[2 * tid + g];        // 4 u16 indices
            float4 f;
            f.x = (float)(a.x & 0xFFFFu);
            f.y = (float)(a.x >> 16);
            f.z = (float)(a.y & 0xFFFFu);
            f.w = (float)(a.y >> 16);
            oidx4[2 * tid + g] = f;
        }
    }

    float* ow = out + (size_t)row * N_COLS;
    float4* ow4 = (float4*)ow;
    float4 z = make_float4(0.f, 0.f, 0.f, 0.f);
    ow4[tid] = z;
    ow4[tid + NT] = z;

    // gather top/bot 20 (idx from sidx; value via tiny L2 gather)
    if (tid < 40) {
        int rnk = (tid < 20) ? tid : (N_COLS - 20 + (tid - 20));
        int idx = (int)sidx[rnk];
        sc_idx[tid] = idx;
        float x = rowp[idx];
        sc_val[tid] = (tid < 20) ? x : -x;
    }
    __syncthreads();  // orders the zero-fill stores before the scatter below

    if (tid < 40) {
        int g0 = (tid < 20) ? 0 : 20;
        float m = -1e30f;
#pragma unroll
        for (int j = 0; j < 20; j++) m = fmaxf(m, sc_val[g0 + j]);
        float s = 0.f;
#pragma unroll
        for (int j = 0; j < 20; j++) s += expf(sc_val[g0 + j] - m);
        float w = expf(sc_val[tid] - m) / s;
        ow[sc_idx[tid]] = (tid < 20) ? w : -w;
    }
}

extern "C" void kernel_launch(void* const* d_in, const int* in_sizes, int n_in,
                              void* d_out, int out_size) {
    const float* in = (const float*)d_in[0];
    float* out = (float*)d_out;
    int total = in_sizes[0];
    int B = total / N_COLS;
    int write_indices = (out_size >= 2 * total) ? 1 : 0;

    cudaFuncSetAttribute(pg_sort_kernel,
                         cudaFuncAttributeMaxDynamicSharedMemorySize, SMEM_BYTES);

    pg_build13<<<1, NT>>>();
    pg_sort_kernel<<<B, NT, SMEM_BYTES>>>(in, out, B, write_indices);
}

// round 13
// speedup vs baseline: 1.4012x; 1.0522x over previous
#include <cuda_runtime.h>
#include <stdint.h>

// Problem: B x N fp32 scores. Outputs (concatenated into float d_out):
//   [0, B*N)      portfolio_weights (sparse +softmax(top20), -softmax(bot20))
//   [B*N, 2*B*N)  sorted_indices of argsort(-scores) as float
#define N_COLS 8192
#define NB     1536   // bucket id space (used ids <= 1500)
#define NT     1024   // threads per CTA (one CTA per row)
#define NWARP  32
#define KBUCK  1500   // equal-probability bucket budget (avg ~5.5/bucket)

// 13-bit-prefix bucket table. For prefix p = dk >> 19:
//   entry = (base << 5) | cells   (base <= 1500 fits 11 bits, cells <= 31)
//   bucket = base + ((dk & 0x7FFFF) * cells) >> 19
__device__ unsigned short g_tab13[8192];

__device__ __forceinline__ float key_to_val(unsigned int dk) {
    unsigned int ukey = ~dk;
    return (ukey & 0x80000000u) ? __uint_as_float(ukey ^ 0x80000000u)
                                : __uint_as_float(~ukey);
}

__device__ __forceinline__ unsigned int desc_key(float x) {
    unsigned int u = __float_as_uint(x);
    unsigned int ukey = (u & 0x80000000u) ? ~u : (u | 0x80000000u);
    return ~ukey;   // ascending key == descending value
}

// Build table in ONE kernel (1 block x 1024 threads).
__global__ void pg_build13() {
    __shared__ unsigned int tmax[NT];
    __shared__ unsigned int fixed[8193];
    int t = threadIdx.x;
    unsigned int v[8];
    unsigned int cm = 0;
#pragma unroll
    for (int i = 0; i < 8; i++) {
        int p = t * 8 + i;
        float x = key_to_val(((unsigned int)p) << 19);
        float F;
        if (!(x == x)) F = (p < 4096) ? 0.f : 1.f;            // NaN prefixes
        else           F = normcdff(-fminf(fmaxf(x, -30.f), 30.f)); // 1-Phi(x)
        int b = (int)floorf(F * (float)KBUCK);
        b = b < 0 ? 0 : (b > KBUCK ? KBUCK : b);
        v[i] = (unsigned int)b;
        cm = max(cm, v[i]);
    }
    tmax[t] = cm;
    __syncthreads();
    for (int d = 1; d < NT; d <<= 1) {
        unsigned int w = (t >= d) ? tmax[t - d] : 0u;
        __syncthreads();
        if (t >= d) tmax[t] = max(tmax[t], w);
        __syncthreads();
    }
    unsigned int run = (t == 0) ? 0u : tmax[t - 1];
#pragma unroll
    for (int i = 0; i < 8; i++) {
        run = max(run, v[i]);
        fixed[t * 8 + i] = run;
    }
    if (t == 0) fixed[8192] = KBUCK;
    __syncthreads();
    for (int p = t; p < 8192; p += NT) {
        unsigned int b0 = fixed[p];
        unsigned int c = fixed[p + 1] - b0;
        if (c > 31u) c = 31u;
        g_tab13[p] = (unsigned short)((b0 << 5) | c);
    }
}

// ---------------------------------------------------------------------------
// Element ownership: warp wid owns elements [wid*256, wid*256+256);
// lane handles idx = wid*256 + k*32 + lane (k-major) so scatter position
// order within a bucket equals ascending original index (exact stable ties).
//
// SMEM layout (bytes):
//   [0,     32768)  keys u32[8192]   scattered keys, bucket-grouped (ph3+)
//   [32768, 49152)  sidx u16[8192]   rank->index (ph4+)
//                   ALIAS: tab13 u16[8192] bucket table (ph0-1 only)
//   [49152, 98304)  whist u8[32][1536] per-warp counts -> excl offs (ph1-3)
//   [98304,104452)  base u32[1537]   global excl bucket offsets + sentinel
//   [104464,104592) wsum u32[32]     scan staging
//   [104592,104752) sc_val f32[40]
//   [104752,104912) sc_idx i32[40]
// Total 104912 B -> two CTAs per SM (209824 <= 228KB) with regs <= 32.
// ---------------------------------------------------------------------------
#define SMEM_BYTES 104912

__global__ void __launch_bounds__(NT, 2)
pg_sort_kernel(const float* __restrict__ in, float* __restrict__ out,
               int B, int write_indices) {
    extern __shared__ unsigned char smem_raw[];
    unsigned int*   keys  = (unsigned int*)smem_raw;
    unsigned short* sidx  = (unsigned short*)(smem_raw + 32768);
    unsigned short* tab13 = (unsigned short*)(smem_raw + 32768);  // alias ph0-1
    unsigned char*  whist = (unsigned char*)(smem_raw + 49152);
    unsigned int*   base  = (unsigned int*)(smem_raw + 98304);
    unsigned int*   wsum  = (unsigned int*)(smem_raw + 104464);
    float* sc_val = (float*)(smem_raw + 104592);
    int*   sc_idx = (int*)  (smem_raw + 104752);

    int row = blockIdx.x;
    int tid = threadIdx.x;
    int lane = tid & 31;
    int wid = tid >> 5;
    const float* rowp = in + (size_t)row * N_COLS;

    // Phase 0: zero per-warp histograms (48KB) + copy table to smem (16KB)
    {
        uint4* wz = (uint4*)whist;
        uint4 z4 = make_uint4(0, 0, 0, 0);
        wz[tid] = z4;
        wz[tid + NT] = z4;
        wz[tid + 2 * NT] = z4;
        unsigned int* tsrc = (unsigned int*)g_tab13;
        unsigned int* tdst = (unsigned int*)tab13;
#pragma unroll
        for (int j = 0; j < 4; j++) tdst[tid + j * NT] = tsrc[tid + j * NT];
    }
    __syncthreads();

    // ---- Phase 1: branchless match-based per-warp ranking (k-major layout)
    unsigned int dk[8];
    unsigned int bk[8];                      // packed (bucket<<8)|warp_rank
    {
        int ebase = wid * 256 + lane;
        float vv[8];
#pragma unroll
        for (int k = 0; k < 8; k++) vv[k] = rowp[ebase + k * 32];  // MLP=8
        unsigned char* wh = whist + wid * NB;
        unsigned int ltmask = (1u << lane) - 1u;
#pragma unroll
        for (int k = 0; k < 8; k++) {
            unsigned int d = desc_key(vv[k]);
            dk[k] = d;
            unsigned int e = (unsigned int)tab13[d >> 19];
            unsigned int b = (e >> 5) + (((d & 0x7FFFFu) * (e & 31u)) >> 19);
            unsigned int mask = __match_any_sync(0xFFFFFFFFu, b);
            unsigned int before = (unsigned int)wh[b];                 // all lanes
            wh[b] = (unsigned char)(before + (unsigned int)__popc(mask)); // same val
            bk[k] = (b << 8) | (before + (unsigned int)__popc(mask & ltmask));
            __syncwarp();
        }
    }
    __syncthreads();

    // ---- Phase 2: SIMD cross-warp exclusive offsets.
    // Thread t < 384 owns buckets [4t, 4t+4): u32 loads process 4 u8
    // counters at once; __vadd4 = per-byte add (no cross-byte carry).
    // Bytes written back are identical to the old per-warp u8 offsets.
    {
        unsigned int run = 0, tsum = 0, inc = 0;
        if (tid < 384) {
#pragma unroll
            for (int w = 0; w < NWARP; w++) {
                unsigned int* p32 = (unsigned int*)(whist + w * NB + 4 * tid);
                unsigned int c = *p32;
                *p32 = run;                    // packed per-warp exclusive
                run = __vadd4(run, c);
            }
            tsum = __dp4a(run, 0x01010101u, 0u);   // total of 4 buckets
            inc = tsum;
#pragma unroll
            for (int d = 1; d < 32; d <<= 1) {
                unsigned int v = __shfl_up_sync(0xFFFFFFFFu, inc, d);
                if (lane >= d) inc += v;
            }
            if (lane == 31) wsum[wid] = inc;
        }
        __syncthreads();
        if (tid < 16) {                        // combine 12 warp totals
            unsigned int w = (tid < 12) ? wsum[tid] : 0u;
            unsigned int wi = w;
#pragma unroll
            for (int d = 1; d < 16; d <<= 1) {
                unsigned int v = __shfl_up_sync(0x0000FFFFu, wi, d);
                if (tid >= d) wi += v;
            }
            wsum[tid] = wi - w;                // exclusive warp offsets
        }
        __syncthreads();
        if (tid < 384) {
            unsigned int b0 = inc - tsum + wsum[wid];
            unsigned int b1 = b0 + (run & 0xFFu);
            unsigned int b2 = b1 + ((run >> 8) & 0xFFu);
            unsigned int b3 = b2 + ((run >> 16) & 0xFFu);
            *(uint4*)(base + 4 * tid) = make_uint4(b0, b1, b2, b3);
        }
        if (tid == 0) base[1536] = N_COLS;     // sentinel
    }
    __syncthreads();   // table reads done; keys[] may now be overwritten

    // ---- Phase 3: scatter keys to exact positions
    {
#pragma unroll
        for (int k = 0; k < 8; k++) {
            unsigned int b = bk[k] >> 8;
            unsigned int r = bk[k] & 0xFFu;
            unsigned int pos = base[b] + (unsigned int)whist[wid * NB + b] + r;
            keys[pos] = dk[k];
            bk[k] = (b << 13) | pos;          // repack (b<=1535:11b, pos:13b)
        }
    }
    __syncthreads();   // whist dead; sidx region may now be written

    // ---- Phase 4: branchless rank by counting u32 keys (vectorized).
    {
        const uint4* k4 = (const uint4*)keys;
#pragma unroll
        for (int k = 0; k < 8; k++) {
            unsigned int b = bk[k] >> 13;
            int pos = (int)(bk[k] & 0x1FFFu);
            int start = (int)base[b];
            int end = (int)base[b + 1];       // sentinel makes this safe
            unsigned int mydk = dk[k];
            int s4 = start >> 2;
            int e4 = (end + 3) >> 2;
            int lt = (s4 << 2) - start;
            int eq = 0;
            for (int j = s4; j < e4; j++) {
                uint4 q = k4[j];
                lt += (int)(q.x < mydk) + (int)(q.y < mydk)
                    + (int)(q.z < mydk) + (int)(q.w < mydk);
                eq += (int)(q.x == mydk) + (int)(q.y == mydk)
                    + (int)(q.z == mydk) + (int)(q.w == mydk);
            }
            int rank = lt;
            if (eq != 1) {                    // rare: exact stable tie-break
                for (int j = start; j < pos; j++)
                    rank += (int)(keys[j] == mydk);
            }
            sidx[start + rank] = (unsigned short)(wid * 256 + k * 32 + lane);
        }
    }
    __syncthreads();

    // ---- Phase 5: outputs
    if (write_indices) {
        float4* oidx4 = (float4*)(out + (size_t)B * N_COLS + (size_t)row * N_COLS);
        const uint2* s2 = (const uint2*)sidx;
#pragma unroll
        for (int g = 0; g < 2; g++) {
            uint2 a = s2[2 * tid + g];        // 4 u16 indices
            float4 f;
            f.x = (float)(a.x & 0xFFFFu);
            f.y = (float)(a.x >> 16);
            f.z = (float)(a.y & 0xFFFFu);
            f.w = (float)(a.y >> 16);
            oidx4[2 * tid + g] = f;
        }
    }

    float* ow = out + (size_t)row * N_COLS;
    float4* ow4 = (float4*)ow;
    float4 z = make_float4(0.f, 0.f, 0.f, 0.f);
    ow4[tid] = z;
    ow4[tid + NT] = z;

    // gather top/bot 20 (idx from sidx; value via tiny L2 gather)
    if (tid < 40) {
        int rnk = (tid < 20) ? tid : (N_COLS - 20 + (tid - 20));
        int idx = (int)sidx[rnk];
        sc_idx[tid] = idx;
        float x = rowp[idx];
        sc_val[tid] = (tid < 20) ? x : -x;
    }
    __syncthreads();  // orders the zero-fill stores before the scatter below

    if (tid < 40) {
        int g0 = (tid < 20) ? 0 : 20;
        float m = -1e30f;
#pragma unroll
        for (int j = 0; j < 20; j++) m = fmaxf(m, sc_val[g0 + j]);
        float s = 0.f;
#pragma unroll
        for (int j = 0; j < 20; j++) s += expf(sc_val[g0 + j] - m);
        float w = expf(sc_val[tid] - m) / s;
        ow[sc_idx[tid]] = (tid < 20) ? w : -w;
    }
}

extern "C" void kernel_launch(void* const* d_in, const int* in_sizes, int n_in,
                              void* d_out, int out_size) {
    const float* in = (const float*)d_in[0];
    float* out = (float*)d_out;
    int total = in_sizes[0];
    int B = total / N_COLS;
    int write_indices = (out_size >= 2 * total) ? 1 : 0;

    cudaFuncSetAttribute(pg_sort_kernel,
                         cudaFuncAttributeMaxDynamicSharedMemorySize, SMEM_BYTES);

    pg_build13<<<1, NT>>>();
    pg_sort_kernel<<<B, NT, SMEM_BYTES>>>(in, out, B, write_indices);
}

// round 14
// speedup vs baseline: 1.4127x; 1.0081x over previous
#include <cuda_runtime.h>
#include <stdint.h>

// Problem: B x N fp32 scores. Outputs (concatenated into float d_out):
//   [0, B*N)      portfolio_weights (sparse +softmax(top20), -softmax(bot20))
//   [B*N, 2*B*N)  sorted_indices of argsort(-scores) as float
#define N_COLS 8192
#define NB     1536   // bucket id space (used ids <= 1500)
#define NT     1024   // threads per CTA (one CTA per row)
#define NWARP  32
#define KBUCK  1500   // equal-probability bucket budget (avg ~5.5/bucket)

// 13-bit-prefix bucket table. For prefix p = dk >> 19:
//   entry = (base << 5) | cells   (base <= 1500 fits 11 bits, cells <= 31)
//   bucket = base + ((dk & 0x7FFFF) * cells) >> 19
__device__ unsigned short g_tab13[8192];

__device__ __forceinline__ float key_to_val(unsigned int dk) {
    unsigned int ukey = ~dk;
    return (ukey & 0x80000000u) ? __uint_as_float(ukey ^ 0x80000000u)
                                : __uint_as_float(~ukey);
}

__device__ __forceinline__ unsigned int desc_key(float x) {
    unsigned int u = __float_as_uint(x);
    unsigned int ukey = (u & 0x80000000u) ? ~u : (u | 0x80000000u);
    return ~ukey;   // ascending key == descending value
}

// Build table in ONE kernel (1 block x 1024 threads).
__global__ void pg_build13() {
    __shared__ unsigned int tmax[NT];
    __shared__ unsigned int fixed[8193];
    int t = threadIdx.x;
    unsigned int v[8];
    unsigned int cm = 0;
#pragma unroll
    for (int i = 0; i < 8; i++) {
        int p = t * 8 + i;
        float x = key_to_val(((unsigned int)p) << 19);
        float F;
        if (!(x == x)) F = (p < 4096) ? 0.f : 1.f;            // NaN prefixes
        else           F = normcdff(-fminf(fmaxf(x, -30.f), 30.f)); // 1-Phi(x)
        int b = (int)floorf(F * (float)KBUCK);
        b = b < 0 ? 0 : (b > KBUCK ? KBUCK : b);
        v[i] = (unsigned int)b;
        cm = max(cm, v[i]);
    }
    tmax[t] = cm;
    __syncthreads();
    for (int d = 1; d < NT; d <<= 1) {
        unsigned int w = (t >= d) ? tmax[t - d] : 0u;
        __syncthreads();
        if (t >= d) tmax[t] = max(tmax[t], w);
        __syncthreads();
    }
    unsigned int run = (t == 0) ? 0u : tmax[t - 1];
#pragma unroll
    for (int i = 0; i < 8; i++) {
        run = max(run, v[i]);
        fixed[t * 8 + i] = run;
    }
    if (t == 0) fixed[8192] = KBUCK;
    __syncthreads();
    for (int p = t; p < 8192; p += NT) {
        unsigned int b0 = fixed[p];
        unsigned int c = fixed[p + 1] - b0;
        if (c > 31u) c = 31u;
        g_tab13[p] = (unsigned short)((b0 << 5) | c);
    }
}

// ---------------------------------------------------------------------------
// Element ownership: warp wid owns elements [wid*256, wid*256+256);
// lane handles idx = wid*256 + k*32 + lane (k-major) so scatter position
// order within a bucket equals ascending original index (exact stable ties).
//
// SMEM layout (bytes):
//   [0,     32768)  keys u32[8192]   scattered keys, bucket-grouped (ph3+)
//   [32768, 49152)  sidx u16[8192]   rank->index (ph4+)
//                   ALIAS: tab13 u16[8192] bucket table (ph0-1 only)
//   [49152, 98304)  whist u8[32][1536] per-warp counts -> excl offs (ph1-3)
//   [98304,104452)  base u32[1537]   global excl bucket offsets + sentinel
//   [104464,104592) wsum u32[32]     scan staging
//   [104592,104752) sc_val f32[40]
//   [104752,104912) sc_idx i32[40]
// Total 104912 B -> two CTAs per SM (209824 <= 228KB) with regs <= 32.
// ---------------------------------------------------------------------------
#define SMEM_BYTES 104912

__global__ void __launch_bounds__(NT, 2)
pg_sort_kernel(const float* __restrict__ in, float* __restrict__ out,
               int B, int write_indices) {
    extern __shared__ unsigned char smem_raw[];
    unsigned int*   keys  = (unsigned int*)smem_raw;
    unsigned short* sidx  = (unsigned short*)(smem_raw + 32768);
    unsigned short* tab13 = (unsigned short*)(smem_raw + 32768);  // alias ph0-1
    unsigned char*  whist = (unsigned char*)(smem_raw + 49152);
    unsigned int*   base  = (unsigned int*)(smem_raw + 98304);
    unsigned int*   wsum  = (unsigned int*)(smem_raw + 104464);
    float* sc_val = (float*)(smem_raw + 104592);
    int*   sc_idx = (int*)  (smem_raw + 104752);

    int row = blockIdx.x;
    int tid = threadIdx.x;
    int lane = tid & 31;
    int wid = tid >> 5;
    const float* rowp = in + (size_t)row * N_COLS;

    // Phase 0: zero per-warp histograms (48KB) + copy table to smem (16KB)
    {
        uint4* wz = (uint4*)whist;
        uint4 z4 = make_uint4(0, 0, 0, 0);
        wz[tid] = z4;
        wz[tid + NT] = z4;
        wz[tid + 2 * NT] = z4;
        unsigned int* tsrc = (unsigned int*)g_tab13;
        unsigned int* tdst = (unsigned int*)tab13;
#pragma unroll
        for (int j = 0; j < 4; j++) tdst[tid + j * NT] = tsrc[tid + j * NT];
    }
    __syncthreads();

    // ---- Phase 1: branchless match-based per-warp ranking (k-major layout)
    unsigned int dk[8];
    unsigned int bk[8];                      // packed (bucket<<8)|warp_rank
    {
        int ebase = wid * 256 + lane;
        float vv[8];
#pragma unroll
        for (int k = 0; k < 8; k++) vv[k] = rowp[ebase + k * 32];  // MLP=8
        unsigned char* wh = whist + wid * NB;
        unsigned int ltmask = (1u << lane) - 1u;
#pragma unroll
        for (int k = 0; k < 8; k++) {
            unsigned int d = desc_key(vv[k]);
            dk[k] = d;
            unsigned int e = (unsigned int)tab13[d >> 19];
            unsigned int b = (e >> 5) + (((d & 0x7FFFFu) * (e & 31u)) >> 19);
            unsigned int mask = __match_any_sync(0xFFFFFFFFu, b);
            unsigned int before = (unsigned int)wh[b];                 // all lanes
            wh[b] = (unsigned char)(before + (unsigned int)__popc(mask)); // same val
            bk[k] = (b << 8) | (before + (unsigned int)__popc(mask & ltmask));
            __syncwarp();
        }
    }
    __syncthreads();

    // ---- Phase 2: SIMD cross-warp exclusive offsets.
    // Thread t < 384 owns buckets [4t, 4t+4): u32 loads process 4 u8
    // counters at once; __vadd4 = per-byte add (no cross-byte carry).
    {
        unsigned int run = 0, tsum = 0, inc = 0;
        if (tid < 384) {
#pragma unroll
            for (int w = 0; w < NWARP; w++) {
                unsigned int* p32 = (unsigned int*)(whist + w * NB + 4 * tid);
                unsigned int c = *p32;
                *p32 = run;                    // packed per-warp exclusive
                run = __vadd4(run, c);
            }
            tsum = __dp4a(run, 0x01010101u, 0u);   // total of 4 buckets
            inc = tsum;
#pragma unroll
            for (int d = 1; d < 32; d <<= 1) {
                unsigned int v = __shfl_up_sync(0xFFFFFFFFu, inc, d);
                if (lane >= d) inc += v;
            }
            if (lane == 31) wsum[wid] = inc;
        }
        __syncthreads();
        if (tid < 16) {                        // combine 12 warp totals
            unsigned int w = (tid < 12) ? wsum[tid] : 0u;
            unsigned int wi = w;
#pragma unroll
            for (int d = 1; d < 16; d <<= 1) {
                unsigned int v = __shfl_up_sync(0x0000FFFFu, wi, d);
                if (tid >= d) wi += v;
            }
            wsum[tid] = wi - w;                // exclusive warp offsets
        }
        __syncthreads();
        if (tid < 384) {
            unsigned int b0 = inc - tsum + wsum[wid];
            unsigned int b1 = b0 + (run & 0xFFu);
            unsigned int b2 = b1 + ((run >> 8) & 0xFFu);
            unsigned int b3 = b2 + ((run >> 16) & 0xFFu);
            *(uint4*)(base + 4 * tid) = make_uint4(b0, b1, b2, b3);
        }
        if (tid == 0) base[1536] = N_COLS;     // sentinel
    }
    __syncthreads();   // table reads done; keys[] may now be overwritten

    // ---- Phase 3: scatter keys to exact positions
    {
#pragma unroll
        for (int k = 0; k < 8; k++) {
            unsigned int b = bk[k] >> 8;
            unsigned int r = bk[k] & 0xFFu;
            unsigned int pos = base[b] + (unsigned int)whist[wid * NB + b] + r;
            keys[pos] = dk[k];
            bk[k] = (b << 13) | pos;          // repack (b<=1535:11b, pos:13b)
        }
    }
    __syncthreads();   // whist dead; sidx region may now be written

    // ---- Phase 4: exact rank, ONE compare per entry.
    // rank = #{key_j < mydk} + #{key_j == mydk && j < pos}:
    //   region [4*s4, 4*p4): count (key <= mydk)   (all j < pos)
    //   mid vector p4:       per-slot (lt | (eq & slot < pos%4))
    //   region (p4, e4):     count (key < mydk)    (all j > pos)
    // Left extras (< start) are strictly smaller -> counted once, pre-
    // subtracted; right extras strictly larger -> contribute 0. Exact for
    // every tie configuration; no tie branch at all.
    {
        const uint4* k4 = (const uint4*)keys;
#pragma unroll
        for (int k = 0; k < 8; k++) {
            unsigned int b = bk[k] >> 13;
            int pos = (int)(bk[k] & 0x1FFFu);
            int start = (int)base[b];
            int end = (int)base[b + 1];       // sentinel makes this safe
            unsigned int mydk = dk[k];
            int s4 = start >> 2;
            int p4 = pos >> 2;
            int e4 = (end + 3) >> 2;
            int rank = (s4 << 2) - start;     // subtract left extras
            for (int j = s4; j < p4; j++) {
                uint4 q = k4[j];
                rank += (int)(q.x <= mydk) + (int)(q.y <= mydk)
                      + (int)(q.z <= mydk) + (int)(q.w <= mydk);
            }
            {
                uint4 q = k4[p4];
                int pm = pos & 3;
                rank += (int)((q.x < mydk) | ((q.x == mydk) & (0 < pm)));
                rank += (int)((q.y < mydk) | ((q.y == mydk) & (1 < pm)));
                rank += (int)((q.z < mydk) | ((q.z == mydk) & (2 < pm)));
                rank += (int)((q.w < mydk) | ((q.w == mydk) & (3 < pm)));
            }
            for (int j = p4 + 1; j < e4; j++) {
                uint4 q = k4[j];
                rank += (int)(q.x < mydk) + (int)(q.y < mydk)
                      + (int)(q.z < mydk) + (int)(q.w < mydk);
            }
            sidx[start + rank] = (unsigned short)(wid * 256 + k * 32 + lane);
        }
    }
    __syncthreads();

    // ---- Phase 5: outputs
    if (write_indices) {
        float4* oidx4 = (float4*)(out + (size_t)B * N_COLS + (size_t)row * N_COLS);
        const uint2* s2 = (const uint2*)sidx;
#pragma unroll
        for (int g = 0; g < 2; g++) {
            uint2 a = s2[2 * tid + g];        // 4 u16 indices
            float4 f;
            f.x = (float)(a.x & 0xFFFFu);
            f.y = (float)(a.x >> 16);
            f.z = (float)(a.y & 0xFFFFu);
            f.w = (float)(a.y >> 16);
            oidx4[2 * tid + g] = f;
        }
    }

    float* ow = out + (size_t)row * N_COLS;
    float4* ow4 = (float4*)ow;
    float4 z = make_float4(0.f, 0.f, 0.f, 0.f);
    ow4[tid] = z;
    ow4[tid + NT] = z;

    // gather top/bot 20 (idx from sidx; value via tiny L2 gather)
    if (tid < 40) {
        int rnk = (tid < 20) ? tid : (N_COLS - 20 + (tid - 20));
        int idx = (int)sidx[rnk];
        sc_idx[tid] = idx;
        float x = rowp[idx];
        sc_val[tid] = (tid < 20) ? x : -x;
    }
    __syncthreads();  // orders the zero-fill stores before the scatter below

    if (tid < 40) {
        int g0 = (tid < 20) ? 0 : 20;
        float m = -1e30f;
#pragma unroll
        for (int j = 0; j < 20; j++) m = fmaxf(m, sc_val[g0 + j]);
        float s = 0.f;
#pragma unroll
        for (int j = 0; j < 20; j++) s += expf(sc_val[g0 + j] - m);
        float w = expf(sc_val[tid] - m) / s;
        ow[sc_idx[tid]] = (tid < 20) ? w : -w;
    }
}

extern "C" void kernel_launch(void* const* d_in, const int* in_sizes, int n_in,
                              void* d_out, int out_size) {
    const float* in = (const float*)d_in[0];
    float* out = (float*)d_out;
    int total = in_sizes[0];
    int B = total / N_COLS;
    int write_indices = (out_size >= 2 * total) ? 1 : 0;

    cudaFuncSetAttribute(pg_sort_kernel,
                         cudaFuncAttributeMaxDynamicSharedMemorySize, SMEM_BYTES);

    pg_build13<<<1, NT>>>();
    pg_sort_kernel<<<B, NT, SMEM_BYTES>>>(in, out, B, write_indices);
}